// round 1
// baseline (speedup 1.0000x reference)
#include <cuda_runtime.h>
#include <math.h>

#define NN   30000
#define EE   510000
#define TT   2
#define FIN  128
#define H1C  128
#define OUTC 64

// ---------------- scratch (device globals; no allocation) ----------------
__device__ float g_h[NN * 256];            // current conv's h = x@W   (max 2C=256)
__device__ float g_di[NN];                 // <h[n], a[:2C]>  (dst term)
__device__ float g_dj[NN];                 // <h[n], a[2C:]>  (src term)
__device__ int   g_deg[TT][NN];
__device__ int   g_cursor[TT][NN];
__device__ int   g_rowptr[TT][NN + 1];
__device__ int   g_csr_src[TT][EE];
__device__ float g_mu1[TT][NN * H1C];      // layer1 outputs (fused+relu'd in place)
__device__ float g_mu2[TT][NN * OUTC];     // layer2 outputs (pre-fusion)
__device__ float g_ixz;                    // sum over 4 convs of sum_{n,c} kl
__device__ float g_skl;                    // sum over 4 convs of sum_e skl-term

// ---------------- setup kernels ----------------
__global__ void zero_kernel() {
    int i = blockIdx.x * blockDim.x + threadIdx.x;
    if (i < NN) {
        g_deg[0][i] = 0; g_deg[1][i] = 0;
        g_cursor[0][i] = 0; g_cursor[1][i] = 0;
    }
    if (i == 0) { g_ixz = 0.f; g_skl = 0.f; }
}

__global__ void hist_kernel(const int* __restrict__ dst, int t) {
    int e = blockIdx.x * blockDim.x + threadIdx.x;
    if (e < EE) atomicAdd(&g_deg[t][dst[e]], 1);
}

// single-block exclusive scan over g_deg[t] -> g_rowptr[t]
__global__ void scan_kernel(int t) {
    __shared__ int wsum[32];
    __shared__ int s_carry;
    int tid = threadIdx.x, lane = tid & 31, wid = tid >> 5;
    if (tid == 0) s_carry = 0;
    __syncthreads();
    for (int base = 0; base < NN; base += 1024) {
        int i = base + tid;
        int v = (i < NN) ? g_deg[t][i] : 0;
        int x = v;
#pragma unroll
        for (int o = 1; o < 32; o <<= 1) {
            int y = __shfl_up_sync(0xffffffffu, x, o);
            if (lane >= o) x += y;
        }
        if (lane == 31) wsum[wid] = x;
        __syncthreads();
        if (wid == 0) {
            int s = wsum[lane];
#pragma unroll
            for (int o = 1; o < 32; o <<= 1) {
                int y = __shfl_up_sync(0xffffffffu, s, o);
                if (lane >= o) s += y;
            }
            wsum[lane] = s;
        }
        __syncthreads();
        int excl = x - v + (wid ? wsum[wid - 1] : 0) + s_carry;
        if (i < NN) g_rowptr[t][i] = excl;
        __syncthreads();
        if (tid == 0) s_carry += wsum[31];
        __syncthreads();
    }
    if (tid == 0) g_rowptr[t][NN] = s_carry;
}

__global__ void scatter_kernel(const int* __restrict__ src,
                               const int* __restrict__ dst, int t) {
    int e = blockIdx.x * blockDim.x + threadIdx.x;
    if (e < EE) {
        int d = dst[e];
        int pos = g_rowptr[t][d] + atomicAdd(&g_cursor[t][d], 1);
        g_csr_src[t][pos] = src[e];
    }
}

// ---------------- SGEMM: C[M,Ncols] = A[M,128] @ B[128,Ncols] ----------------
__global__ void __launch_bounds__(256)
sgemm_128(const float* __restrict__ A, const float* __restrict__ B,
          float* __restrict__ Cmat, int M, int Ncols) {
    __shared__ float As[16][128 + 4];
    __shared__ float Bs[16][128];
    int tid = threadIdx.x;
    int brow = blockIdx.x * 128;
    int bcol = blockIdx.y * 128;
    int tx = tid & 15;   // 0..15  -> 8 cols each
    int ty = tid >> 4;   // 0..15  -> 8 rows each
    float acc[8][8];
#pragma unroll
    for (int i = 0; i < 8; i++)
#pragma unroll
        for (int j = 0; j < 8; j++) acc[i][j] = 0.f;

    for (int k0 = 0; k0 < 128; k0 += 16) {
#pragma unroll
        for (int p = 0; p < 2; p++) {
            int r = (tid >> 2) + p * 64;
            int c = (tid & 3) * 4;
            float4 v = make_float4(0.f, 0.f, 0.f, 0.f);
            int gr = brow + r;
            if (gr < M) v = *(const float4*)(A + (size_t)gr * 128 + k0 + c);
            As[c + 0][r] = v.x; As[c + 1][r] = v.y;
            As[c + 2][r] = v.z; As[c + 3][r] = v.w;
        }
#pragma unroll
        for (int p = 0; p < 2; p++) {
            int r = (tid >> 5) + p * 8;
            int c = (tid & 31) * 4;
            *(float4*)&Bs[r][c] = *(const float4*)(B + (size_t)(k0 + r) * Ncols + bcol + c);
        }
        __syncthreads();
#pragma unroll
        for (int kk = 0; kk < 16; kk++) {
            float a[8], b[8];
#pragma unroll
            for (int i = 0; i < 8; i++) a[i] = As[kk][ty * 8 + i];
#pragma unroll
            for (int j = 0; j < 8; j++) b[j] = Bs[kk][tx * 8 + j];
#pragma unroll
            for (int i = 0; i < 8; i++)
#pragma unroll
                for (int j = 0; j < 8; j++) acc[i][j] += a[i] * b[j];
        }
        __syncthreads();
    }
#pragma unroll
    for (int i = 0; i < 8; i++) {
        int gr = brow + ty * 8 + i;
        if (gr >= M) continue;
#pragma unroll
        for (int j = 0; j < 8; j += 4) {
            float4 v = make_float4(acc[i][j], acc[i][j + 1], acc[i][j + 2], acc[i][j + 3]);
            *(float4*)(Cmat + (size_t)gr * Ncols + bcol + tx * 8 + j) = v;
        }
    }
}

// ---------------- per-node attention dot products ----------------
__global__ void dots_kernel(const float* __restrict__ h,
                            const float* __restrict__ att, int twoC) {
    int gw = (blockIdx.x * blockDim.x + threadIdx.x) >> 5;
    int lane = threadIdx.x & 31;
    if (gw >= NN) return;
    const float* hr = h + (size_t)gw * twoC;
    float si = 0.f, sj = 0.f;
    for (int c = lane * 4; c < twoC; c += 128) {
        float4 hv = *(const float4*)(hr + c);
        float4 ai = *(const float4*)(att + c);
        float4 aj = *(const float4*)(att + twoC + c);
        si += hv.x * ai.x + hv.y * ai.y + hv.z * ai.z + hv.w * ai.w;
        sj += hv.x * aj.x + hv.y * aj.y + hv.z * aj.z + hv.w * aj.w;
    }
#pragma unroll
    for (int off = 16; off; off >>= 1) {
        si += __shfl_xor_sync(0xffffffffu, si, off);
        sj += __shfl_xor_sync(0xffffffffu, sj, off);
    }
    if (lane == 0) { g_di[gw] = si; g_dj[gw] = sj; }
}

// ---------------- fused aggregation + epilogue (warp per node) ----------------
template <int C>
__global__ void agg_kernel(const float* __restrict__ h,
                           const float* __restrict__ bvec,
                           float* __restrict__ mu_out, int t) {
    constexpr int PL = C / 32;   // mu channels per lane (4 or 2)
    int gw = (blockIdx.x * blockDim.x + threadIdx.x) >> 5;
    int lane = threadIdx.x & 31;
    if (gw >= NN) return;
    int beg = g_rowptr[t][gw], end = g_rowptr[t][gw + 1];
    float dvi = g_di[gw];
    float invdeg = 1.f / (float)(end - beg);
    float accM[PL], accS[PL];
#pragma unroll
    for (int k = 0; k < PL; k++) { accM[k] = 0.f; accS[k] = 0.f; }
    float skl = 0.f;
    const float q = 1.f / (1.f + expf(-(1.f / 15.f)));
    const float logq = logf(q), log1mq = logf(1.f - q);

    for (int pos = beg; pos < end; pos++) {
        int s = g_csr_src[t][pos];
        float lg = dvi + g_dj[s];
        lg = lg > 0.f ? lg : 0.2f * lg;                 // leaky_relu 0.2
        float p = 1.f / (1.f + expf(-lg));
        p = fminf(fmaxf(p, 0.01f), 0.99f);
        float alpha = p * invdeg;
        if (lane == 0)
            skl += p * (logf(p) - logq) + (1.f - p) * (logf(1.f - p) - log1mq);
        const float* hr = h + (size_t)s * (2 * C);
        if constexpr (PL == 4) {
            float4 m  = *(const float4*)(hr + lane * 4);
            float4 sv = *(const float4*)(hr + C + lane * 4);
            accM[0] += alpha * m.x;  accM[1] += alpha * m.y;
            accM[2] += alpha * m.z;  accM[3] += alpha * m.w;
            accS[0] += alpha * sv.x; accS[1] += alpha * sv.y;
            accS[2] += alpha * sv.z; accS[3] += alpha * sv.w;
        } else {
            float2 m  = *(const float2*)(hr + lane * 2);
            float2 sv = *(const float2*)(hr + C + lane * 2);
            accM[0] += alpha * m.x;  accM[1] += alpha * m.y;
            accS[0] += alpha * sv.x; accS[1] += alpha * sv.y;
        }
    }
#pragma unroll
    for (int k = 0; k < PL; k++) {
        accM[k] += bvec[lane * PL + k];
        accS[k] += bvec[C + lane * PL + k];
    }
    if constexpr (PL == 4) {
        *(float4*)(mu_out + (size_t)gw * C + lane * 4) =
            make_float4(accM[0], accM[1], accM[2], accM[3]);
    } else {
        *(float2*)(mu_out + (size_t)gw * C + lane * 2) =
            make_float2(accM[0], accM[1]);
    }
    float kls = 0.f;
#pragma unroll
    for (int k = 0; k < PL; k++) {
        float x = accS[k];
        float sp = fmaxf(x, 0.f) + log1pf(expf(-fabsf(x)));   // softplus
        float sd = sp + 1e-10f;
        float m = accM[k];
        kls += -logf(sd) + 0.5f * (sd * sd + m * m) - 0.5f;
    }
#pragma unroll
    for (int off = 16; off; off >>= 1) {
        kls += __shfl_xor_sync(0xffffffffu, kls, off);
        skl += __shfl_xor_sync(0xffffffffu, skl, off);
    }
    if (lane == 0) { atomicAdd(&g_ixz, kls); atomicAdd(&g_skl, skl); }
}

// ---------------- temporal fusion ----------------
// layer1: x2[0]=relu(mu0); x2[1]=relu(0.4*mu0 + 0.2*mu1)   (in place on g_mu1)
__global__ void fuse_relu_kernel(float* __restrict__ mu1) {
    size_t i = (size_t)blockIdx.x * blockDim.x + threadIdx.x;
    const size_t total = (size_t)NN * H1C;
    if (i < total) {
        float a = mu1[i], b = mu1[total + i];
        mu1[i] = fmaxf(a, 0.f);
        mu1[total + i] = fmaxf(0.4f * a + 0.2f * b, 0.f);
    }
}

// final: out[0]=mu2_0 ; out[1]=0.4*mu2_0+0.2*mu2_1 ; scalars
__global__ void final_kernel(const float* __restrict__ mu2,
                             float* __restrict__ out, int out_size) {
    int i = blockIdx.x * blockDim.x + threadIdx.x;
    const int total = NN * OUTC;
    if (i < total) {
        float a = mu2[i], b = mu2[total + i];
        if (i < out_size) out[i] = a;
        if (total + i < out_size) out[total + i] = 0.4f * a + 0.2f * b;
    }
    if (i == 0) {
        if (2 * total < out_size)     out[2 * total]     = g_ixz / (4.0f * NN);
        if (2 * total + 1 < out_size) out[2 * total + 1] = g_skl / (4.0f * EE);
    }
}

// ---------------- launch ----------------
extern "C" void kernel_launch(void* const* d_in, const int* in_sizes, int n_in,
                              void* d_out, int out_size) {
    const float* x_all = (const float*)d_in[0];
    const int*   ei    = (const int*)d_in[1];
    const float* W1    = (const float*)d_in[2];
    const float* att1  = (const float*)d_in[3];
    const float* b1    = (const float*)d_in[4];
    const float* W2    = (const float*)d_in[5];
    const float* att2  = (const float*)d_in[6];
    const float* b2    = (const float*)d_in[7];
    float* out = (float*)d_out;

    float *p_h, *p_mu1, *p_mu2;
    cudaGetSymbolAddress((void**)&p_h,   g_h);
    cudaGetSymbolAddress((void**)&p_mu1, g_mu1);
    cudaGetSymbolAddress((void**)&p_mu2, g_mu2);

    zero_kernel<<<(NN + 255) / 256, 256>>>();

    // CSR build per snapshot (shared by both layers)
    for (int t = 0; t < TT; t++) {
        const int* src = ei + (size_t)t * 2 * EE;
        const int* dst = src + EE;
        hist_kernel<<<(EE + 255) / 256, 256>>>(dst, t);
    }
    for (int t = 0; t < TT; t++) scan_kernel<<<1, 1024>>>(t);
    for (int t = 0; t < TT; t++) {
        const int* src = ei + (size_t)t * 2 * EE;
        const int* dst = src + EE;
        scatter_kernel<<<(EE + 255) / 256, 256>>>(src, dst, t);
    }

    dim3 g1((NN + 127) / 128, 2);   // Ncols=256
    dim3 g2((NN + 127) / 128, 1);   // Ncols=128
    int warpBlocks = (NN + 7) / 8;  // 8 warps per 256-thread block

    // layer 1
    for (int t = 0; t < TT; t++) {
        sgemm_128<<<g1, 256>>>(x_all + (size_t)t * NN * FIN, W1, p_h, NN, 2 * H1C);
        dots_kernel<<<warpBlocks, 256>>>(p_h, att1, 2 * H1C);
        agg_kernel<H1C><<<warpBlocks, 256>>>(p_h, b1, p_mu1 + (size_t)t * NN * H1C, t);
    }
    fuse_relu_kernel<<<(NN * H1C + 255) / 256, 256>>>(p_mu1);

    // layer 2
    for (int t = 0; t < TT; t++) {
        sgemm_128<<<g2, 256>>>(p_mu1 + (size_t)t * NN * H1C, W2, p_h, NN, 2 * OUTC);
        dots_kernel<<<warpBlocks, 256>>>(p_h, att2, 2 * OUTC);
        agg_kernel<OUTC><<<warpBlocks, 256>>>(p_h, b2, p_mu2 + (size_t)t * NN * OUTC, t);
    }

    final_kernel<<<(NN * OUTC + 255) / 256, 256>>>(p_mu2, out, out_size);
}

// round 2
// speedup vs baseline: 1.0326x; 1.0326x over previous
#include <cuda_runtime.h>
#include <math.h>

#define NN   30000
#define EE   510000
#define TT   2
#define FIN  128
#define H1C  128
#define OUTC 64

// ---------------- scratch (device globals; no allocation) ----------------
__device__ float g_h[TT][NN * 256];        // per-snapshot h = x@W (max 2C=256)
__device__ float g_di[TT][NN];             // <h[n], a[:2C]>  (dst term)
__device__ float g_dj[TT][NN];             // <h[n], a[2C:]>  (src term)
__device__ int   g_deg[TT][NN];
__device__ int   g_cursor[TT][NN];
__device__ int   g_rowptr[TT][NN + 1];
__device__ int   g_csr_src[TT][EE];
__device__ float g_mu1[TT][NN * H1C];      // layer1 outputs (fused+relu'd in place)
__device__ float g_mu2[TT][NN * OUTC];     // layer2 outputs (pre-fusion)
__device__ float g_ixz;
__device__ float g_skl;

// ---------------- setup kernels ----------------
__global__ void zero_kernel() {
    int i = blockIdx.x * blockDim.x + threadIdx.x;
    if (i < NN) {
        g_deg[0][i] = 0; g_deg[1][i] = 0;
        g_cursor[0][i] = 0; g_cursor[1][i] = 0;
    }
    if (i == 0) { g_ixz = 0.f; g_skl = 0.f; }
}

// fused histogram over both snapshots
__global__ void hist2_kernel(const int* __restrict__ ei) {
    int i = blockIdx.x * blockDim.x + threadIdx.x;
    if (i < 2 * EE) {
        int t = (i >= EE) ? 1 : 0;
        int e = i - t * EE;
        int d = ei[(size_t)t * 2 * EE + EE + e];
        atomicAdd(&g_deg[t][d], 1);
    }
}

// single-pass scan: one block per snapshot, 30 elements/thread in registers
__global__ void scan2_kernel() {
    const int P = 30;             // 1024*30 = 30720 >= NN
    int t = blockIdx.x;
    __shared__ int wsum[32];
    int tid = threadIdx.x, lane = tid & 31, wid = tid >> 5;
    int base = tid * P;
    int loc[P];
    int s = 0;
#pragma unroll
    for (int j = 0; j < P; j++) {
        int idx = base + j;
        int v = (idx < NN) ? g_deg[t][idx] : 0;
        loc[j] = s;               // exclusive local prefix
        s += v;
    }
    int inc = s;                  // inclusive warp scan of thread totals
#pragma unroll
    for (int o = 1; o < 32; o <<= 1) {
        int y = __shfl_up_sync(0xffffffffu, inc, o);
        if (lane >= o) inc += y;
    }
    if (lane == 31) wsum[wid] = inc;
    __syncthreads();
    if (wid == 0) {
        int w = wsum[lane];
#pragma unroll
        for (int o = 1; o < 32; o <<= 1) {
            int y = __shfl_up_sync(0xffffffffu, w, o);
            if (lane >= o) w += y;
        }
        wsum[lane] = w;
    }
    __syncthreads();
    int off = inc - s + (wid ? wsum[wid - 1] : 0);
#pragma unroll
    for (int j = 0; j < P; j++) {
        int idx = base + j;
        if (idx < NN) g_rowptr[t][idx] = off + loc[j];
    }
    if (tid == 1023) g_rowptr[t][NN] = off + s;
}

// fused scatter over both snapshots
__global__ void scatter2_kernel(const int* __restrict__ ei) {
    int i = blockIdx.x * blockDim.x + threadIdx.x;
    if (i < 2 * EE) {
        int t = (i >= EE) ? 1 : 0;
        int e = i - t * EE;
        const int* src = ei + (size_t)t * 2 * EE;
        const int* dst = src + EE;
        int d = dst[e];
        int pos = g_rowptr[t][d] + atomicAdd(&g_cursor[t][d], 1);
        g_csr_src[t][pos] = src[e];
    }
}

// ---------------- SGEMM: C[M,Ncols] = A[M,128] @ B[128,Ncols] ----------------
// double-buffered smem, register-staged prefetch, 1 sync/chunk, 2 CTAs/SM
__global__ void __launch_bounds__(256, 2)
sgemm_128(const float* __restrict__ A, const float* __restrict__ B,
          float* __restrict__ Cmat, int M, int Ncols) {
    __shared__ float As[2][16][132];
    __shared__ float Bs[2][16][128];
    int tid = threadIdx.x;
    int brow = blockIdx.x * 128;
    int bcol = blockIdx.y * 128;
    int tx = tid & 15;
    int ty = tid >> 4;

    int ar = tid >> 2;            // 0..63 (+p*64)
    int ac = (tid & 3) * 4;       // k within chunk
    int br = tid >> 5;            // 0..7 (+p*8)
    int bc = (tid & 31) * 4;

    float4 aReg[2], bReg[2];
    float acc[8][8];
#pragma unroll
    for (int i = 0; i < 8; i++)
#pragma unroll
        for (int j = 0; j < 8; j++) acc[i][j] = 0.f;

#define LDG_CHUNK(k0)                                                          \
    {                                                                          \
        _Pragma("unroll")                                                      \
        for (int p = 0; p < 2; p++) {                                          \
            int gr = brow + ar + p * 64;                                       \
            aReg[p] = (gr < M) ? *(const float4*)(A + (size_t)gr * 128 + (k0) + ac) \
                               : make_float4(0.f, 0.f, 0.f, 0.f);              \
            bReg[p] = *(const float4*)(B + (size_t)((k0) + br + p * 8) * Ncols + bcol + bc); \
        }                                                                      \
    }
#define STS_CHUNK(buf)                                                         \
    {                                                                          \
        _Pragma("unroll")                                                      \
        for (int p = 0; p < 2; p++) {                                          \
            int r = ar + p * 64;                                               \
            As[buf][ac + 0][r] = aReg[p].x; As[buf][ac + 1][r] = aReg[p].y;    \
            As[buf][ac + 2][r] = aReg[p].z; As[buf][ac + 3][r] = aReg[p].w;    \
            *(float4*)&Bs[buf][br + p * 8][bc] = bReg[p];                      \
        }                                                                      \
    }
#define COMPUTE(buf)                                                           \
    {                                                                          \
        _Pragma("unroll")                                                      \
        for (int kk = 0; kk < 16; kk++) {                                      \
            float a[8], b[8];                                                  \
            *(float4*)&a[0] = *(const float4*)&As[buf][kk][ty * 8];            \
            *(float4*)&a[4] = *(const float4*)&As[buf][kk][ty * 8 + 4];        \
            *(float4*)&b[0] = *(const float4*)&Bs[buf][kk][tx * 8];            \
            *(float4*)&b[4] = *(const float4*)&Bs[buf][kk][tx * 8 + 4];        \
            _Pragma("unroll")                                                  \
            for (int i = 0; i < 8; i++)                                        \
                _Pragma("unroll")                                              \
                for (int j = 0; j < 8; j++) acc[i][j] += a[i] * b[j];          \
        }                                                                      \
    }

    LDG_CHUNK(0);
    STS_CHUNK(0);
    __syncthreads();
#pragma unroll
    for (int c = 0; c < 8; c++) {
        if (c < 7) LDG_CHUNK((c + 1) * 16);
        COMPUTE(c & 1);
        if (c < 7) {
            STS_CHUNK((c + 1) & 1);
            __syncthreads();
        }
    }
#undef LDG_CHUNK
#undef STS_CHUNK
#undef COMPUTE

#pragma unroll
    for (int i = 0; i < 8; i++) {
        int gr = brow + ty * 8 + i;
        if (gr >= M) continue;
#pragma unroll
        for (int j = 0; j < 8; j += 4) {
            float4 v = make_float4(acc[i][j], acc[i][j + 1], acc[i][j + 2], acc[i][j + 3]);
            *(float4*)(Cmat + (size_t)gr * Ncols + bcol + tx * 8 + j) = v;
        }
    }
}

// ---------------- per-node attention dot products ----------------
__global__ void dots_kernel(const float* __restrict__ h,
                            const float* __restrict__ att, int twoC, int t) {
    int gw = (blockIdx.x * blockDim.x + threadIdx.x) >> 5;
    int lane = threadIdx.x & 31;
    if (gw >= NN) return;
    const float* hr = h + (size_t)gw * twoC;
    float si = 0.f, sj = 0.f;
    for (int c = lane * 4; c < twoC; c += 128) {
        float4 hv = *(const float4*)(hr + c);
        float4 ai = *(const float4*)(att + c);
        float4 aj = *(const float4*)(att + twoC + c);
        si += hv.x * ai.x + hv.y * ai.y + hv.z * ai.z + hv.w * ai.w;
        sj += hv.x * aj.x + hv.y * aj.y + hv.z * aj.z + hv.w * aj.w;
    }
#pragma unroll
    for (int off = 16; off; off >>= 1) {
        si += __shfl_xor_sync(0xffffffffu, si, off);
        sj += __shfl_xor_sync(0xffffffffu, sj, off);
    }
    if (lane == 0) { g_di[t][gw] = si; g_dj[t][gw] = sj; }
}

// ---------------- fused aggregation + epilogue (warp per node) ----------------
template <int C>
__global__ void agg_kernel(const float* __restrict__ h,
                           const float* __restrict__ bvec,
                           float* __restrict__ mu_out, int t) {
    constexpr int PL = C / 32;
    int gw = (blockIdx.x * blockDim.x + threadIdx.x) >> 5;
    int lane = threadIdx.x & 31;
    if (gw >= NN) return;
    int beg = g_rowptr[t][gw], end = g_rowptr[t][gw + 1];
    float dvi = g_di[t][gw];
    float invdeg = 1.f / (float)(end - beg);
    float accM[PL], accS[PL];
#pragma unroll
    for (int k = 0; k < PL; k++) { accM[k] = 0.f; accS[k] = 0.f; }
    float skl = 0.f;
    const float q = 1.f / (1.f + expf(-(1.f / 15.f)));
    const float logq = logf(q), log1mq = logf(1.f - q);

    for (int pos = beg; pos < end; pos++) {
        int s = g_csr_src[t][pos];
        float lg = dvi + g_dj[t][s];
        lg = lg > 0.f ? lg : 0.2f * lg;
        float p = 1.f / (1.f + expf(-lg));
        p = fminf(fmaxf(p, 0.01f), 0.99f);
        float alpha = p * invdeg;
        if (lane == 0)
            skl += p * (logf(p) - logq) + (1.f - p) * (logf(1.f - p) - log1mq);
        const float* hr = h + (size_t)s * (2 * C);
        if constexpr (PL == 4) {
            float4 m  = *(const float4*)(hr + lane * 4);
            float4 sv = *(const float4*)(hr + C + lane * 4);
            accM[0] += alpha * m.x;  accM[1] += alpha * m.y;
            accM[2] += alpha * m.z;  accM[3] += alpha * m.w;
            accS[0] += alpha * sv.x; accS[1] += alpha * sv.y;
            accS[2] += alpha * sv.z; accS[3] += alpha * sv.w;
        } else {
            float2 m  = *(const float2*)(hr + lane * 2);
            float2 sv = *(const float2*)(hr + C + lane * 2);
            accM[0] += alpha * m.x;  accM[1] += alpha * m.y;
            accS[0] += alpha * sv.x; accS[1] += alpha * sv.y;
        }
    }
#pragma unroll
    for (int k = 0; k < PL; k++) {
        accM[k] += bvec[lane * PL + k];
        accS[k] += bvec[C + lane * PL + k];
    }
    if constexpr (PL == 4) {
        *(float4*)(mu_out + (size_t)gw * C + lane * 4) =
            make_float4(accM[0], accM[1], accM[2], accM[3]);
    } else {
        *(float2*)(mu_out + (size_t)gw * C + lane * 2) =
            make_float2(accM[0], accM[1]);
    }
    float kls = 0.f;
#pragma unroll
    for (int k = 0; k < PL; k++) {
        float x = accS[k];
        float sp = fmaxf(x, 0.f) + log1pf(expf(-fabsf(x)));
        float sd = sp + 1e-10f;
        float m = accM[k];
        kls += -logf(sd) + 0.5f * (sd * sd + m * m) - 0.5f;
    }
#pragma unroll
    for (int off = 16; off; off >>= 1) {
        kls += __shfl_xor_sync(0xffffffffu, kls, off);
        skl += __shfl_xor_sync(0xffffffffu, skl, off);
    }
    if (lane == 0) { atomicAdd(&g_ixz, kls); atomicAdd(&g_skl, skl); }
}

// ---------------- temporal fusion ----------------
__global__ void fuse_relu_kernel(float* __restrict__ mu1) {
    size_t i = (size_t)blockIdx.x * blockDim.x + threadIdx.x;
    const size_t total = (size_t)NN * H1C;
    if (i < total) {
        float a = mu1[i], b = mu1[total + i];
        mu1[i] = fmaxf(a, 0.f);
        mu1[total + i] = fmaxf(0.4f * a + 0.2f * b, 0.f);
    }
}

__global__ void final_kernel(const float* __restrict__ mu2,
                             float* __restrict__ out, int out_size) {
    int i = blockIdx.x * blockDim.x + threadIdx.x;
    const int total = NN * OUTC;
    if (i < total) {
        float a = mu2[i], b = mu2[total + i];
        if (i < out_size) out[i] = a;
        if (total + i < out_size) out[total + i] = 0.4f * a + 0.2f * b;
    }
    if (i == 0) {
        if (2 * total < out_size)     out[2 * total]     = g_ixz / (4.0f * NN);
        if (2 * total + 1 < out_size) out[2 * total + 1] = g_skl / (4.0f * EE);
    }
}

// ---------------- launch ----------------
extern "C" void kernel_launch(void* const* d_in, const int* in_sizes, int n_in,
                              void* d_out, int out_size) {
    const float* x_all = (const float*)d_in[0];
    const int*   ei    = (const int*)d_in[1];
    const float* W1    = (const float*)d_in[2];
    const float* att1  = (const float*)d_in[3];
    const float* b1    = (const float*)d_in[4];
    const float* W2    = (const float*)d_in[5];
    const float* att2  = (const float*)d_in[6];
    const float* b2    = (const float*)d_in[7];
    float* out = (float*)d_out;

    float *p_h0, *p_h1, *p_mu1, *p_mu2;
    cudaGetSymbolAddress((void**)&p_h0, g_h);
    p_h1 = p_h0 + (size_t)NN * 256;
    cudaGetSymbolAddress((void**)&p_mu1, g_mu1);
    cudaGetSymbolAddress((void**)&p_mu2, g_mu2);
    float* p_h[2] = {p_h0, p_h1};

    zero_kernel<<<(NN + 255) / 256, 256>>>();
    hist2_kernel<<<(2 * EE + 255) / 256, 256>>>(ei);
    scan2_kernel<<<2, 1024>>>();
    scatter2_kernel<<<(2 * EE + 255) / 256, 256>>>(ei);

    dim3 g1((NN + 127) / 128, 2);   // Ncols=256
    dim3 g2((NN + 127) / 128, 1);   // Ncols=128
    int warpBlocks = (NN + 7) / 8;

    // layer 1 (gemms first so ncu -s 5 lands on gemm t1)
    for (int t = 0; t < TT; t++)
        sgemm_128<<<g1, 256>>>(x_all + (size_t)t * NN * FIN, W1, p_h[t], NN, 2 * H1C);
    for (int t = 0; t < TT; t++)
        dots_kernel<<<warpBlocks, 256>>>(p_h[t], att1, 2 * H1C, t);
    for (int t = 0; t < TT; t++)
        agg_kernel<H1C><<<warpBlocks, 256>>>(p_h[t], b1, p_mu1 + (size_t)t * NN * H1C, t);
    fuse_relu_kernel<<<(NN * H1C + 255) / 256, 256>>>(p_mu1);

    // layer 2
    for (int t = 0; t < TT; t++)
        sgemm_128<<<g2, 256>>>(p_mu1 + (size_t)t * NN * H1C, W2, p_h[t], NN, 2 * OUTC);
    for (int t = 0; t < TT; t++)
        dots_kernel<<<warpBlocks, 256>>>(p_h[t], att2, 2 * OUTC, t);
    for (int t = 0; t < TT; t++)
        agg_kernel<OUTC><<<warpBlocks, 256>>>(p_h[t], b2, p_mu2 + (size_t)t * NN * OUTC, t);

    final_kernel<<<(NN * OUTC + 255) / 256, 256>>>(p_mu2, out, out_size);
}

// round 5
// speedup vs baseline: 1.1923x; 1.1547x over previous
#include <cuda_runtime.h>
#include <cuda_bf16.h>
#include <stdint.h>
#include <math.h>

#define NN   30000
#define EE   510000
#define TT   2
#define FIN  128
#define H1C  128
#define OUTC 64

// ---------------- scratch (device globals; no allocation) ----------------
__device__ float g_h[TT][NN * 256];        // per-snapshot h = x@W (max 2C=256)
__device__ float g_di[TT][NN];
__device__ float g_dj[TT][NN];
__device__ int   g_deg[TT][NN];
__device__ int   g_cursor[TT][NN];
__device__ int   g_rowptr[TT][NN + 1];
__device__ int   g_csr_src[TT][EE];
__device__ float g_mu1[TT][NN * H1C];
__device__ float g_mu2[TT][NN * OUTC];
__device__ float g_ixz;
__device__ float g_skl;
// weights as bf16 hi/lo in per-lane mma-fragment order:
// index = ((g*8 + s)*2 + r)*32 + lane, b32 = halves (k, k+1)
//   g = n-tile (n = g*8 + lane>>2), s = kstep, r: k = s*16 + (lane&3)*2 + r*8
__device__ uint32_t g_B1h[256 * 64];
__device__ uint32_t g_B1l[256 * 64];
__device__ uint32_t g_B2h[128 * 64];
__device__ uint32_t g_B2l[128 * 64];

// ---------------- mma.sync helper (family-common, works on compute_103) ----
__device__ __forceinline__ void mma16816(float* c, const uint32_t* a, const uint32_t* b) {
    asm volatile(
        "mma.sync.aligned.m16n8k16.row.col.f32.bf16.bf16.f32 "
        "{%0,%1,%2,%3}, {%4,%5,%6,%7}, {%8,%9}, {%0,%1,%2,%3};"
        : "+f"(c[0]), "+f"(c[1]), "+f"(c[2]), "+f"(c[3])
        : "r"(a[0]), "r"(a[1]), "r"(a[2]), "r"(a[3]), "r"(b[0]), "r"(b[1]));
}

// ---------------- setup kernels ----------------
__global__ void zero_kernel() {
    int i = blockIdx.x * blockDim.x + threadIdx.x;
    if (i < NN) {
        g_deg[0][i] = 0; g_deg[1][i] = 0;
        g_cursor[0][i] = 0; g_cursor[1][i] = 0;
    }
    if (i == 0) { g_ixz = 0.f; g_skl = 0.f; }
}

__global__ void hist2_kernel(const int* __restrict__ ei) {
    int i = blockIdx.x * blockDim.x + threadIdx.x;
    if (i < 2 * EE) {
        int t = (i >= EE) ? 1 : 0;
        int e = i - t * EE;
        int d = ei[(size_t)t * 2 * EE + EE + e];
        atomicAdd(&g_deg[t][d], 1);
    }
}

__global__ void scan2_kernel() {
    const int P = 30;
    int t = blockIdx.x;
    __shared__ int wsum[32];
    int tid = threadIdx.x, lane = tid & 31, wid = tid >> 5;
    int base = tid * P;
    int loc[P];
    int s = 0;
#pragma unroll
    for (int j = 0; j < P; j++) {
        int idx = base + j;
        int v = (idx < NN) ? g_deg[t][idx] : 0;
        loc[j] = s;
        s += v;
    }
    int inc = s;
#pragma unroll
    for (int o = 1; o < 32; o <<= 1) {
        int y = __shfl_up_sync(0xffffffffu, inc, o);
        if (lane >= o) inc += y;
    }
    if (lane == 31) wsum[wid] = inc;
    __syncthreads();
    if (wid == 0) {
        int w = wsum[lane];
#pragma unroll
        for (int o = 1; o < 32; o <<= 1) {
            int y = __shfl_up_sync(0xffffffffu, w, o);
            if (lane >= o) w += y;
        }
        wsum[lane] = w;
    }
    __syncthreads();
    int off = inc - s + (wid ? wsum[wid - 1] : 0);
#pragma unroll
    for (int j = 0; j < P; j++) {
        int idx = base + j;
        if (idx < NN) g_rowptr[t][idx] = off + loc[j];
    }
    if (tid == 1023) g_rowptr[t][NN] = off + s;
}

__global__ void scatter2_kernel(const int* __restrict__ ei) {
    int i = blockIdx.x * blockDim.x + threadIdx.x;
    if (i < 2 * EE) {
        int t = (i >= EE) ? 1 : 0;
        int e = i - t * EE;
        const int* src = ei + (size_t)t * 2 * EE;
        const int* dst = src + EE;
        int d = dst[e];
        int pos = g_rowptr[t][d] + atomicAdd(&g_cursor[t][d], 1);
        g_csr_src[t][pos] = src[e];
    }
}

// W fp32 [K=128, Ncols] -> bf16 hi/lo fragments (per-lane order)
__global__ void convB_kernel(const float* __restrict__ W,
                             uint32_t* __restrict__ Bh,
                             uint32_t* __restrict__ Bl, int Ncols) {
    int i = blockIdx.x * blockDim.x + threadIdx.x;
    if (i >= Ncols * 64) return;
    int l = i & 31, r = (i >> 5) & 1, s = (i >> 6) & 7, g = i >> 9;
    int n = g * 8 + (l >> 2);
    int k = s * 16 + (l & 3) * 2 + r * 8;
    float v0 = W[(size_t)k * Ncols + n];
    float v1 = W[(size_t)(k + 1) * Ncols + n];
    __nv_bfloat162 h2 = __floats2bfloat162_rn(v0, v1);
    float rx = v0 - __bfloat162float(h2.x);
    float ry = v1 - __bfloat162float(h2.y);
    __nv_bfloat162 l2 = __floats2bfloat162_rn(rx, ry);
    Bh[i] = *(uint32_t*)&h2;
    Bl[i] = *(uint32_t*)&l2;
}

// ---------------- HMMA GEMM: C[M, NCOLS] = A[M,128] @ B ----------------
// bf16-split 3-term (AhBh + AhBl + AlBh), fp32 accumulate in registers.
// CTA tile 128x128, 8 warps (2m x 4n), warp tile 64x32 (4x4 mma tiles).
template <int NCOLS>
__global__ void __launch_bounds__(256, 1)
gemm_mma(const float* __restrict__ A,
         const uint32_t* __restrict__ Bh, const uint32_t* __restrict__ Bl,
         float* __restrict__ Cmat, int M) {
    extern __shared__ char smem[];
    // A hi at [0, 34816), A lo at [34816, 69632): 128 rows x 136 halves (272B stride)
    const int AL_OFF = 34816;
    uint32_t* sBh = (uint32_t*)(smem + 69632);   // 8192 b32
    uint32_t* sBl = sBh + 8192;                  // 8192 b32
    int tid = threadIdx.x, wid = tid >> 5, l = tid & 31;
    int brow = blockIdx.x * 128, bcol = blockIdx.y * 128;

    // B fragments: bulk copy (region per n-128-block is contiguous: 16 g's x 512 b32)
    {
        const uint32_t* gH = Bh + (size_t)blockIdx.y * 16 * 512;
        const uint32_t* gL = Bl + (size_t)blockIdx.y * 16 * 512;
        for (int i = tid; i < 8192; i += 256) { sBh[i] = gH[i]; sBl[i] = gL[i]; }
    }
    // A: load fp32, split hi/lo, store to padded smem
    for (int i = tid; i < 128 * 64; i += 256) {
        int row = i >> 6, kp = i & 63;           // kp = float2 index
        int gr = brow + row;
        float2 v = make_float2(0.f, 0.f);
        if (gr < M) v = *(const float2*)(A + (size_t)gr * 128 + kp * 2);
        __nv_bfloat162 h2 = __floats2bfloat162_rn(v.x, v.y);
        float rx = v.x - __bfloat162float(h2.x);
        float ry = v.y - __bfloat162float(h2.y);
        __nv_bfloat162 l2 = __floats2bfloat162_rn(rx, ry);
        int hoff = row * 136 + kp * 2;           // halves
        *(uint32_t*)(smem + hoff * 2) = *(uint32_t*)&h2;
        *(uint32_t*)(smem + AL_OFF + hoff * 2) = *(uint32_t*)&l2;
    }
    __syncthreads();

    int wm = wid >> 2, wn = wid & 3;             // 2 x 4 warp grid
    float acc[4][4][4];
#pragma unroll
    for (int mt = 0; mt < 4; mt++)
#pragma unroll
        for (int nt = 0; nt < 4; nt++)
#pragma unroll
            for (int k = 0; k < 4; k++) acc[mt][nt][k] = 0.f;

    int arow = wm * 64 + (l >> 2);               // fragment base row for this lane
    int acol = (l & 3) * 2;                      // fragment base k (halves)

    for (int s = 0; s < 8; s++) {
        uint32_t aH[4][4], aL[4][4];
#pragma unroll
        for (int mt = 0; mt < 4; mt++) {
            int r0 = arow + mt * 16;
            int c0 = s * 16 + acol;
            int o00 = (r0 * 136 + c0) * 2;
            int o10 = ((r0 + 8) * 136 + c0) * 2;
            aH[mt][0] = *(uint32_t*)(smem + o00);
            aH[mt][1] = *(uint32_t*)(smem + o10);
            aH[mt][2] = *(uint32_t*)(smem + o00 + 16);
            aH[mt][3] = *(uint32_t*)(smem + o10 + 16);
            aL[mt][0] = *(uint32_t*)(smem + AL_OFF + o00);
            aL[mt][1] = *(uint32_t*)(smem + AL_OFF + o10);
            aL[mt][2] = *(uint32_t*)(smem + AL_OFF + o00 + 16);
            aL[mt][3] = *(uint32_t*)(smem + AL_OFF + o10 + 16);
        }
        uint32_t bH[4][2], bL[4][2];
#pragma unroll
        for (int nt = 0; nt < 4; nt++) {
            int g = wn * 4 + nt;
            int base = ((g * 8 + s) * 2) * 32 + l;
            bH[nt][0] = sBh[base]; bH[nt][1] = sBh[base + 32];
            bL[nt][0] = sBl[base]; bL[nt][1] = sBl[base + 32];
        }
#pragma unroll
        for (int mt = 0; mt < 4; mt++)
#pragma unroll
            for (int nt = 0; nt < 4; nt++) {
                mma16816(acc[mt][nt], aH[mt], bH[nt]);
                mma16816(acc[mt][nt], aH[mt], bL[nt]);
                mma16816(acc[mt][nt], aL[mt], bH[nt]);
            }
    }

    // epilogue: C fragment rows = l>>2 (+8), cols = (l&3)*2 + {0,1}
#pragma unroll
    for (int mt = 0; mt < 4; mt++) {
        int r0 = brow + wm * 64 + mt * 16 + (l >> 2);
#pragma unroll
        for (int nt = 0; nt < 4; nt++) {
            int c0 = bcol + wn * 32 + nt * 8 + (l & 3) * 2;
            if (r0 < M)
                *(float2*)(Cmat + (size_t)r0 * NCOLS + c0) =
                    make_float2(acc[mt][nt][0], acc[mt][nt][1]);
            if (r0 + 8 < M)
                *(float2*)(Cmat + (size_t)(r0 + 8) * NCOLS + c0) =
                    make_float2(acc[mt][nt][2], acc[mt][nt][3]);
        }
    }
}

// ---------------- per-node attention dot products ----------------
__global__ void dots_kernel(const float* __restrict__ h,
                            const float* __restrict__ att, int twoC, int t) {
    int gw = (blockIdx.x * blockDim.x + threadIdx.x) >> 5;
    int lane = threadIdx.x & 31;
    if (gw >= NN) return;
    const float* hr = h + (size_t)gw * twoC;
    float si = 0.f, sj = 0.f;
    for (int c = lane * 4; c < twoC; c += 128) {
        float4 hv = *(const float4*)(hr + c);
        float4 ai = *(const float4*)(att + c);
        float4 aj = *(const float4*)(att + twoC + c);
        si += hv.x * ai.x + hv.y * ai.y + hv.z * ai.z + hv.w * ai.w;
        sj += hv.x * aj.x + hv.y * aj.y + hv.z * aj.z + hv.w * aj.w;
    }
#pragma unroll
    for (int off = 16; off; off >>= 1) {
        si += __shfl_xor_sync(0xffffffffu, si, off);
        sj += __shfl_xor_sync(0xffffffffu, sj, off);
    }
    if (lane == 0) { g_di[t][gw] = si; g_dj[t][gw] = sj; }
}

// ---------------- fused aggregation + epilogue (warp per node) ----------------
template <int C>
__global__ void agg_kernel(const float* __restrict__ h,
                           const float* __restrict__ bvec,
                           float* __restrict__ mu_out, int t) {
    constexpr int PL = C / 32;
    int gw = (blockIdx.x * blockDim.x + threadIdx.x) >> 5;
    int lane = threadIdx.x & 31;
    if (gw >= NN) return;
    int beg = g_rowptr[t][gw], end = g_rowptr[t][gw + 1];
    float dvi = g_di[t][gw];
    float invdeg = 1.f / (float)(end - beg);
    float accM[PL], accS[PL];
#pragma unroll
    for (int k = 0; k < PL; k++) { accM[k] = 0.f; accS[k] = 0.f; }
    float skl = 0.f;
    const float q = 1.f / (1.f + expf(-(1.f / 15.f)));
    const float logq = logf(q), log1mq = logf(1.f - q);

    for (int pos = beg; pos < end; pos++) {
        int s = g_csr_src[t][pos];
        float lg = dvi + g_dj[t][s];
        lg = lg > 0.f ? lg : 0.2f * lg;
        float p = 1.f / (1.f + expf(-lg));
        p = fminf(fmaxf(p, 0.01f), 0.99f);
        float alpha = p * invdeg;
        if (lane == 0)
            skl += p * (logf(p) - logq) + (1.f - p) * (logf(1.f - p) - log1mq);
        const float* hr = h + (size_t)s * (2 * C);
        if constexpr (PL == 4) {
            float4 m  = *(const float4*)(hr + lane * 4);
            float4 sv = *(const float4*)(hr + C + lane * 4);
            accM[0] += alpha * m.x;  accM[1] += alpha * m.y;
            accM[2] += alpha * m.z;  accM[3] += alpha * m.w;
            accS[0] += alpha * sv.x; accS[1] += alpha * sv.y;
            accS[2] += alpha * sv.z; accS[3] += alpha * sv.w;
        } else {
            float2 m  = *(const float2*)(hr + lane * 2);
            float2 sv = *(const float2*)(hr + C + lane * 2);
            accM[0] += alpha * m.x;  accM[1] += alpha * m.y;
            accS[0] += alpha * sv.x; accS[1] += alpha * sv.y;
        }
    }
#pragma unroll
    for (int k = 0; k < PL; k++) {
        accM[k] += bvec[lane * PL + k];
        accS[k] += bvec[C + lane * PL + k];
    }
    if constexpr (PL == 4) {
        *(float4*)(mu_out + (size_t)gw * C + lane * 4) =
            make_float4(accM[0], accM[1], accM[2], accM[3]);
    } else {
        *(float2*)(mu_out + (size_t)gw * C + lane * 2) =
            make_float2(accM[0], accM[1]);
    }
    float kls = 0.f;
#pragma unroll
    for (int k = 0; k < PL; k++) {
        float x = accS[k];
        float sp = fmaxf(x, 0.f) + log1pf(expf(-fabsf(x)));
        float sd = sp + 1e-10f;
        float m = accM[k];
        kls += -logf(sd) + 0.5f * (sd * sd + m * m) - 0.5f;
    }
#pragma unroll
    for (int off = 16; off; off >>= 1) {
        kls += __shfl_xor_sync(0xffffffffu, kls, off);
        skl += __shfl_xor_sync(0xffffffffu, skl, off);
    }
    if (lane == 0) { atomicAdd(&g_ixz, kls); atomicAdd(&g_skl, skl); }
}

// ---------------- temporal fusion ----------------
__global__ void fuse_relu_kernel(float* __restrict__ mu1) {
    size_t i = (size_t)blockIdx.x * blockDim.x + threadIdx.x;
    const size_t total = (size_t)NN * H1C;
    if (i < total) {
        float a = mu1[i], b = mu1[total + i];
        mu1[i] = fmaxf(a, 0.f);
        mu1[total + i] = fmaxf(0.4f * a + 0.2f * b, 0.f);
    }
}

__global__ void final_kernel(const float* __restrict__ mu2,
                             float* __restrict__ out, int out_size) {
    int i = blockIdx.x * blockDim.x + threadIdx.x;
    const int total = NN * OUTC;
    if (i < total) {
        float a = mu2[i], b = mu2[total + i];
        if (i < out_size) out[i] = a;
        if (total + i < out_size) out[total + i] = 0.4f * a + 0.2f * b;
    }
    if (i == 0) {
        if (2 * total < out_size)     out[2 * total]     = g_ixz / (4.0f * NN);
        if (2 * total + 1 < out_size) out[2 * total + 1] = g_skl / (4.0f * EE);
    }
}

// ---------------- launch ----------------
extern "C" void kernel_launch(void* const* d_in, const int* in_sizes, int n_in,
                              void* d_out, int out_size) {
    const float* x_all = (const float*)d_in[0];
    const int*   ei    = (const int*)d_in[1];
    const float* W1    = (const float*)d_in[2];
    const float* att1  = (const float*)d_in[3];
    const float* b1    = (const float*)d_in[4];
    const float* W2    = (const float*)d_in[5];
    const float* att2  = (const float*)d_in[6];
    const float* b2    = (const float*)d_in[7];
    float* out = (float*)d_out;

    float *p_h0, *p_h1, *p_mu1, *p_mu2;
    cudaGetSymbolAddress((void**)&p_h0, g_h);
    p_h1 = p_h0 + (size_t)NN * 256;
    cudaGetSymbolAddress((void**)&p_mu1, g_mu1);
    cudaGetSymbolAddress((void**)&p_mu2, g_mu2);
    float* p_h[2] = {p_h0, p_h1};
    uint32_t *p_B1h, *p_B1l, *p_B2h, *p_B2l;
    cudaGetSymbolAddress((void**)&p_B1h, g_B1h);
    cudaGetSymbolAddress((void**)&p_B1l, g_B1l);
    cudaGetSymbolAddress((void**)&p_B2h, g_B2h);
    cudaGetSymbolAddress((void**)&p_B2l, g_B2l);

    const int GSMEM = 69632 + 2 * 8192 * 4;   // 135168 bytes
    static bool attr_done = false;
    if (!attr_done) {
        cudaFuncSetAttribute(gemm_mma<256>, cudaFuncAttributeMaxDynamicSharedMemorySize, GSMEM);
        cudaFuncSetAttribute(gemm_mma<128>, cudaFuncAttributeMaxDynamicSharedMemorySize, GSMEM);
        attr_done = true;
    }

    zero_kernel<<<(NN + 255) / 256, 256>>>();                         // 1
    hist2_kernel<<<(2 * EE + 255) / 256, 256>>>(ei);                  // 2
    scan2_kernel<<<2, 1024>>>();                                      // 3
    scatter2_kernel<<<(2 * EE + 255) / 256, 256>>>(ei);               // 4
    convB_kernel<<<(256 * 64 + 255) / 256, 256>>>(W1, p_B1h, p_B1l, 256);   // 5

    int gBlocks = (NN + 127) / 128;   // 235
    int warpBlocks = (NN + 7) / 8;

    // layer 1 (gemm t0 is launch #6 -> profiled by ncu -s 5 -c 1)
    for (int t = 0; t < TT; t++)
        gemm_mma<256><<<dim3(gBlocks, 2), 256, GSMEM>>>(
            x_all + (size_t)t * NN * FIN, p_B1h, p_B1l, p_h[t], NN);
    convB_kernel<<<(128 * 64 + 255) / 256, 256>>>(W2, p_B2h, p_B2l, 128);
    for (int t = 0; t < TT; t++)
        dots_kernel<<<warpBlocks, 256>>>(p_h[t], att1, 2 * H1C, t);
    for (int t = 0; t < TT; t++)
        agg_kernel<H1C><<<warpBlocks, 256>>>(p_h[t], b1, p_mu1 + (size_t)t * NN * H1C, t);
    fuse_relu_kernel<<<(NN * H1C + 255) / 256, 256>>>(p_mu1);

    // layer 2
    for (int t = 0; t < TT; t++)
        gemm_mma<128><<<dim3(gBlocks, 1), 256, GSMEM>>>(
            p_mu1 + (size_t)t * NN * H1C, p_B2h, p_B2l, p_h[t], NN);
    for (int t = 0; t < TT; t++)
        dots_kernel<<<warpBlocks, 256>>>(p_h[t], att2, 2 * OUTC, t);
    for (int t = 0; t < TT; t++)
        agg_kernel<OUTC><<<warpBlocks, 256>>>(p_h[t], b2, p_mu2 + (size_t)t * NN * OUTC, t);

    final_kernel<<<(NN * OUTC + 255) / 256, 256>>>(p_mu2, out, out_size);
}

// round 6
// speedup vs baseline: 1.4249x; 1.1951x over previous
#include <cuda_runtime.h>
#include <cuda_bf16.h>
#include <stdint.h>
#include <math.h>

#define NN   30000
#define EE   510000
#define TT   2
#define FIN  128
#define H1C  128
#define OUTC 64

// ---------------- scratch (device globals; no allocation) ----------------
__device__ float g_h[TT][NN * 256];        // per-snapshot h = x@W (max 2C=256)
__device__ float g_di[TT][NN];
__device__ float g_dj[TT][NN];
__device__ int   g_deg[TT][NN];
__device__ int   g_cursor[TT][NN];
__device__ int   g_rowptr[TT][NN + 1];
__device__ int   g_csr_src[TT][EE];
__device__ float g_mu1[TT][NN * H1C];
__device__ float g_mu2[TT][NN * OUTC];
__device__ float g_ixz;
__device__ float g_skl;
// weights as bf16 hi/lo in per-lane mma-fragment order
__device__ uint32_t g_B1h[256 * 64];
__device__ uint32_t g_B1l[256 * 64];
__device__ uint32_t g_B2h[128 * 64];
__device__ uint32_t g_B2l[128 * 64];

// ---------------- mma.sync helper (family-common, works on compute_103) ----
__device__ __forceinline__ void mma16816(float* c, const uint32_t* a, const uint32_t* b) {
    asm volatile(
        "mma.sync.aligned.m16n8k16.row.col.f32.bf16.bf16.f32 "
        "{%0,%1,%2,%3}, {%4,%5,%6,%7}, {%8,%9}, {%0,%1,%2,%3};"
        : "+f"(c[0]), "+f"(c[1]), "+f"(c[2]), "+f"(c[3])
        : "r"(a[0]), "r"(a[1]), "r"(a[2]), "r"(a[3]), "r"(b[0]), "r"(b[1]));
}

// ---------------- setup kernels ----------------
__global__ void zero_kernel() {
    int i = blockIdx.x * blockDim.x + threadIdx.x;
    if (i < NN) {
        g_deg[0][i] = 0; g_deg[1][i] = 0;
        g_cursor[0][i] = 0; g_cursor[1][i] = 0;
    }
    if (i == 0) { g_ixz = 0.f; g_skl = 0.f; }
}

__global__ void hist2_kernel(const int* __restrict__ ei) {
    int i = blockIdx.x * blockDim.x + threadIdx.x;
    if (i < 2 * EE) {
        int t = (i >= EE) ? 1 : 0;
        int e = i - t * EE;
        int d = ei[(size_t)t * 2 * EE + EE + e];
        atomicAdd(&g_deg[t][d], 1);
    }
}

__global__ void scan2_kernel() {
    const int P = 30;
    int t = blockIdx.x;
    __shared__ int wsum[32];
    int tid = threadIdx.x, lane = tid & 31, wid = tid >> 5;
    int base = tid * P;
    int loc[P];
    int s = 0;
#pragma unroll
    for (int j = 0; j < P; j++) {
        int idx = base + j;
        int v = (idx < NN) ? g_deg[t][idx] : 0;
        loc[j] = s;
        s += v;
    }
    int inc = s;
#pragma unroll
    for (int o = 1; o < 32; o <<= 1) {
        int y = __shfl_up_sync(0xffffffffu, inc, o);
        if (lane >= o) inc += y;
    }
    if (lane == 31) wsum[wid] = inc;
    __syncthreads();
    if (wid == 0) {
        int w = wsum[lane];
#pragma unroll
        for (int o = 1; o < 32; o <<= 1) {
            int y = __shfl_up_sync(0xffffffffu, w, o);
            if (lane >= o) w += y;
        }
        wsum[lane] = w;
    }
    __syncthreads();
    int off = inc - s + (wid ? wsum[wid - 1] : 0);
#pragma unroll
    for (int j = 0; j < P; j++) {
        int idx = base + j;
        if (idx < NN) g_rowptr[t][idx] = off + loc[j];
    }
    if (tid == 1023) g_rowptr[t][NN] = off + s;
}

__global__ void scatter2_kernel(const int* __restrict__ ei) {
    int i = blockIdx.x * blockDim.x + threadIdx.x;
    if (i < 2 * EE) {
        int t = (i >= EE) ? 1 : 0;
        int e = i - t * EE;
        const int* src = ei + (size_t)t * 2 * EE;
        const int* dst = src + EE;
        int d = dst[e];
        int pos = g_rowptr[t][d] + atomicAdd(&g_cursor[t][d], 1);
        g_csr_src[t][pos] = src[e];
    }
}

// W fp32 [K=128, Ncols] -> bf16 hi/lo fragments (per-lane order)
__global__ void convB_kernel(const float* __restrict__ W,
                             uint32_t* __restrict__ Bh,
                             uint32_t* __restrict__ Bl, int Ncols) {
    int i = blockIdx.x * blockDim.x + threadIdx.x;
    if (i >= Ncols * 64) return;
    int l = i & 31, r = (i >> 5) & 1, s = (i >> 6) & 7, g = i >> 9;
    int n = g * 8 + (l >> 2);
    int k = s * 16 + (l & 3) * 2 + r * 8;
    float v0 = W[(size_t)k * Ncols + n];
    float v1 = W[(size_t)(k + 1) * Ncols + n];
    __nv_bfloat162 h2 = __floats2bfloat162_rn(v0, v1);
    float rx = v0 - __bfloat162float(h2.x);
    float ry = v1 - __bfloat162float(h2.y);
    __nv_bfloat162 l2 = __floats2bfloat162_rn(rx, ry);
    Bh[i] = *(uint32_t*)&h2;
    Bl[i] = *(uint32_t*)&l2;
}

// ---------------- HMMA GEMM: C[M, NCOLS] = A[M,128] @ B ----------------
template <int NCOLS>
__global__ void __launch_bounds__(256, 1)
gemm_mma(const float* __restrict__ A,
         const uint32_t* __restrict__ Bh, const uint32_t* __restrict__ Bl,
         float* __restrict__ Cmat, int M) {
    extern __shared__ char smem[];
    const int AL_OFF = 34816;
    uint32_t* sBh = (uint32_t*)(smem + 69632);
    uint32_t* sBl = sBh + 8192;
    int tid = threadIdx.x, wid = tid >> 5, l = tid & 31;
    int brow = blockIdx.x * 128, bcol = blockIdx.y * 128;

    {
        const uint32_t* gH = Bh + (size_t)blockIdx.y * 16 * 512;
        const uint32_t* gL = Bl + (size_t)blockIdx.y * 16 * 512;
        for (int i = tid; i < 8192; i += 256) { sBh[i] = gH[i]; sBl[i] = gL[i]; }
    }
    for (int i = tid; i < 128 * 64; i += 256) {
        int row = i >> 6, kp = i & 63;
        int gr = brow + row;
        float2 v = make_float2(0.f, 0.f);
        if (gr < M) v = *(const float2*)(A + (size_t)gr * 128 + kp * 2);
        __nv_bfloat162 h2 = __floats2bfloat162_rn(v.x, v.y);
        float rx = v.x - __bfloat162float(h2.x);
        float ry = v.y - __bfloat162float(h2.y);
        __nv_bfloat162 l2 = __floats2bfloat162_rn(rx, ry);
        int hoff = row * 136 + kp * 2;
        *(uint32_t*)(smem + hoff * 2) = *(uint32_t*)&h2;
        *(uint32_t*)(smem + AL_OFF + hoff * 2) = *(uint32_t*)&l2;
    }
    __syncthreads();

    int wm = wid >> 2, wn = wid & 3;
    float acc[4][4][4];
#pragma unroll
    for (int mt = 0; mt < 4; mt++)
#pragma unroll
        for (int nt = 0; nt < 4; nt++)
#pragma unroll
            for (int k = 0; k < 4; k++) acc[mt][nt][k] = 0.f;

    int arow = wm * 64 + (l >> 2);
    int acol = (l & 3) * 2;

    for (int s = 0; s < 8; s++) {
        uint32_t aH[4][4], aL[4][4];
#pragma unroll
        for (int mt = 0; mt < 4; mt++) {
            int r0 = arow + mt * 16;
            int c0 = s * 16 + acol;
            int o00 = (r0 * 136 + c0) * 2;
            int o10 = ((r0 + 8) * 136 + c0) * 2;
            aH[mt][0] = *(uint32_t*)(smem + o00);
            aH[mt][1] = *(uint32_t*)(smem + o10);
            aH[mt][2] = *(uint32_t*)(smem + o00 + 16);
            aH[mt][3] = *(uint32_t*)(smem + o10 + 16);
            aL[mt][0] = *(uint32_t*)(smem + AL_OFF + o00);
            aL[mt][1] = *(uint32_t*)(smem + AL_OFF + o10);
            aL[mt][2] = *(uint32_t*)(smem + AL_OFF + o00 + 16);
            aL[mt][3] = *(uint32_t*)(smem + AL_OFF + o10 + 16);
        }
        uint32_t bH[4][2], bL[4][2];
#pragma unroll
        for (int nt = 0; nt < 4; nt++) {
            int g = wn * 4 + nt;
            int base = ((g * 8 + s) * 2) * 32 + l;
            bH[nt][0] = sBh[base]; bH[nt][1] = sBh[base + 32];
            bL[nt][0] = sBl[base]; bL[nt][1] = sBl[base + 32];
        }
#pragma unroll
        for (int mt = 0; mt < 4; mt++)
#pragma unroll
            for (int nt = 0; nt < 4; nt++) {
                mma16816(acc[mt][nt], aH[mt], bH[nt]);
                mma16816(acc[mt][nt], aH[mt], bL[nt]);
                mma16816(acc[mt][nt], aL[mt], bH[nt]);
            }
    }

#pragma unroll
    for (int mt = 0; mt < 4; mt++) {
        int r0 = brow + wm * 64 + mt * 16 + (l >> 2);
#pragma unroll
        for (int nt = 0; nt < 4; nt++) {
            int c0 = bcol + wn * 32 + nt * 8 + (l & 3) * 2;
            if (r0 < M)
                *(float2*)(Cmat + (size_t)r0 * NCOLS + c0) =
                    make_float2(acc[mt][nt][0], acc[mt][nt][1]);
            if (r0 + 8 < M)
                *(float2*)(Cmat + (size_t)(r0 + 8) * NCOLS + c0) =
                    make_float2(acc[mt][nt][2], acc[mt][nt][3]);
        }
    }
}

// ---------------- per-node attention dot products ----------------
__global__ void dots_kernel(const float* __restrict__ h,
                            const float* __restrict__ att, int twoC, int t) {
    int gw = (blockIdx.x * blockDim.x + threadIdx.x) >> 5;
    int lane = threadIdx.x & 31;
    if (gw >= NN) return;
    const float* hr = h + (size_t)gw * twoC;
    float si = 0.f, sj = 0.f;
    for (int c = lane * 4; c < twoC; c += 128) {
        float4 hv = *(const float4*)(hr + c);
        float4 ai = *(const float4*)(att + c);
        float4 aj = *(const float4*)(att + twoC + c);
        si += hv.x * ai.x + hv.y * ai.y + hv.z * ai.z + hv.w * ai.w;
        sj += hv.x * aj.x + hv.y * aj.y + hv.z * aj.z + hv.w * aj.w;
    }
#pragma unroll
    for (int off = 16; off; off >>= 1) {
        si += __shfl_xor_sync(0xffffffffu, si, off);
        sj += __shfl_xor_sync(0xffffffffu, sj, off);
    }
    if (lane == 0) { g_di[t][gw] = si; g_dj[t][gw] = sj; }
}

// ---------------- fused aggregation (lane-parallel attention, pipelined) ----
template <int C>
__global__ void agg_kernel(const float* __restrict__ h,
                           const float* __restrict__ bvec,
                           float* __restrict__ mu_out, int t) {
    constexpr int PL = C / 32;
    int gw = (blockIdx.x * blockDim.x + threadIdx.x) >> 5;
    int lane = threadIdx.x & 31;
    if (gw >= NN) return;
    int beg = g_rowptr[t][gw], end = g_rowptr[t][gw + 1];
    float dvi = g_di[t][gw];
    float invdeg = 1.f / (float)(end - beg);
    float accM[PL], accS[PL];
#pragma unroll
    for (int k = 0; k < PL; k++) { accM[k] = 0.f; accS[k] = 0.f; }
    float skl = 0.f;
    const float q = 1.f / (1.f + expf(-(1.f / 15.f)));
    const float logq = logf(q), log1mq = logf(1.f - q);

    for (int base = beg; base < end; base += 32) {
        int n = min(32, end - base);
        // lane-parallel: resolve indices + attention for up to 32 edges at once
        int idx = 0;
        float alpha = 0.f;
        if (lane < n) {
            idx = g_csr_src[t][base + lane];
            float lg = dvi + g_dj[t][idx];
            lg = lg > 0.f ? lg : 0.2f * lg;
            float p = 1.f / (1.f + expf(-lg));
            p = fminf(fmaxf(p, 0.01f), 0.99f);
            alpha = p * invdeg;
            skl += p * (logf(p) - logq) + (1.f - p) * (logf(1.f - p) - log1mq);
        }
        // software-pipelined gather over resolved indices (depth 2)
        int s0 = __shfl_sync(0xffffffffu, idx, 0);
        float aNext = __shfl_sync(0xffffffffu, alpha, 0);
        const float* hr = h + (size_t)s0 * (2 * C);
        if constexpr (PL == 4) {
            float4 mN = *(const float4*)(hr + lane * 4);
            float4 sN = *(const float4*)(hr + C + lane * 4);
            for (int j = 0; j < n; j++) {
                float4 mC = mN, sC = sN;
                float aC = aNext;
                if (j + 1 < n) {
                    int s1 = __shfl_sync(0xffffffffu, idx, j + 1);
                    aNext = __shfl_sync(0xffffffffu, alpha, j + 1);
                    const float* hr1 = h + (size_t)s1 * (2 * C);
                    mN = *(const float4*)(hr1 + lane * 4);
                    sN = *(const float4*)(hr1 + C + lane * 4);
                }
                accM[0] += aC * mC.x; accM[1] += aC * mC.y;
                accM[2] += aC * mC.z; accM[3] += aC * mC.w;
                accS[0] += aC * sC.x; accS[1] += aC * sC.y;
                accS[2] += aC * sC.z; accS[3] += aC * sC.w;
            }
        } else {
            float2 mN = *(const float2*)(hr + lane * 2);
            float2 sN = *(const float2*)(hr + C + lane * 2);
            for (int j = 0; j < n; j++) {
                float2 mC = mN, sC = sN;
                float aC = aNext;
                if (j + 1 < n) {
                    int s1 = __shfl_sync(0xffffffffu, idx, j + 1);
                    aNext = __shfl_sync(0xffffffffu, alpha, j + 1);
                    const float* hr1 = h + (size_t)s1 * (2 * C);
                    mN = *(const float2*)(hr1 + lane * 2);
                    sN = *(const float2*)(hr1 + C + lane * 2);
                }
                accM[0] += aC * mC.x; accM[1] += aC * mC.y;
                accS[0] += aC * sC.x; accS[1] += aC * sC.y;
            }
        }
    }
#pragma unroll
    for (int k = 0; k < PL; k++) {
        accM[k] += bvec[lane * PL + k];
        accS[k] += bvec[C + lane * PL + k];
    }
    if constexpr (PL == 4) {
        *(float4*)(mu_out + (size_t)gw * C + lane * 4) =
            make_float4(accM[0], accM[1], accM[2], accM[3]);
    } else {
        *(float2*)(mu_out + (size_t)gw * C + lane * 2) =
            make_float2(accM[0], accM[1]);
    }
    float kls = 0.f;
#pragma unroll
    for (int k = 0; k < PL; k++) {
        float x = accS[k];
        float sp = fmaxf(x, 0.f) + log1pf(expf(-fabsf(x)));
        float sd = sp + 1e-10f;
        float m = accM[k];
        kls += -logf(sd) + 0.5f * (sd * sd + m * m) - 0.5f;
    }
#pragma unroll
    for (int off = 16; off; off >>= 1) {
        kls += __shfl_xor_sync(0xffffffffu, kls, off);
        skl += __shfl_xor_sync(0xffffffffu, skl, off);
    }
    if (lane == 0) { atomicAdd(&g_ixz, kls); atomicAdd(&g_skl, skl); }
}

// ---------------- temporal fusion ----------------
__global__ void fuse_relu_kernel(float* __restrict__ mu1) {
    size_t i = (size_t)blockIdx.x * blockDim.x + threadIdx.x;
    const size_t total = (size_t)NN * H1C;
    if (i < total) {
        float a = mu1[i], b = mu1[total + i];
        mu1[i] = fmaxf(a, 0.f);
        mu1[total + i] = fmaxf(0.4f * a + 0.2f * b, 0.f);
    }
}

__global__ void final_kernel(const float* __restrict__ mu2,
                             float* __restrict__ out, int out_size) {
    int i = blockIdx.x * blockDim.x + threadIdx.x;
    const int total = NN * OUTC;
    if (i < total) {
        float a = mu2[i], b = mu2[total + i];
        if (i < out_size) out[i] = a;
        if (total + i < out_size) out[total + i] = 0.4f * a + 0.2f * b;
    }
    if (i == 0) {
        if (2 * total < out_size)     out[2 * total]     = g_ixz / (4.0f * NN);
        if (2 * total + 1 < out_size) out[2 * total + 1] = g_skl / (4.0f * EE);
    }
}

// ---------------- launch ----------------
extern "C" void kernel_launch(void* const* d_in, const int* in_sizes, int n_in,
                              void* d_out, int out_size) {
    const float* x_all = (const float*)d_in[0];
    const int*   ei    = (const int*)d_in[1];
    const float* W1    = (const float*)d_in[2];
    const float* att1  = (const float*)d_in[3];
    const float* b1    = (const float*)d_in[4];
    const float* W2    = (const float*)d_in[5];
    const float* att2  = (const float*)d_in[6];
    const float* b2    = (const float*)d_in[7];
    float* out = (float*)d_out;

    float *p_h0, *p_h1, *p_mu1, *p_mu2;
    cudaGetSymbolAddress((void**)&p_h0, g_h);
    p_h1 = p_h0 + (size_t)NN * 256;
    cudaGetSymbolAddress((void**)&p_mu1, g_mu1);
    cudaGetSymbolAddress((void**)&p_mu2, g_mu2);
    float* p_h[2] = {p_h0, p_h1};
    uint32_t *p_B1h, *p_B1l, *p_B2h, *p_B2l;
    cudaGetSymbolAddress((void**)&p_B1h, g_B1h);
    cudaGetSymbolAddress((void**)&p_B1l, g_B1l);
    cudaGetSymbolAddress((void**)&p_B2h, g_B2h);
    cudaGetSymbolAddress((void**)&p_B2l, g_B2l);

    const int GSMEM = 69632 + 2 * 8192 * 4;   // 135168 bytes
    static bool attr_done = false;
    if (!attr_done) {
        cudaFuncSetAttribute(gemm_mma<256>, cudaFuncAttributeMaxDynamicSharedMemorySize, GSMEM);
        cudaFuncSetAttribute(gemm_mma<128>, cudaFuncAttributeMaxDynamicSharedMemorySize, GSMEM);
        attr_done = true;
    }

    zero_kernel<<<(NN + 255) / 256, 256>>>();
    hist2_kernel<<<(2 * EE + 255) / 256, 256>>>(ei);
    scan2_kernel<<<2, 1024>>>();
    scatter2_kernel<<<(2 * EE + 255) / 256, 256>>>(ei);
    convB_kernel<<<(256 * 64 + 255) / 256, 256>>>(W1, p_B1h, p_B1l, 256);

    int gBlocks = (NN + 127) / 128;
    int warpBlocks = (NN + 7) / 8;

    // layer 1
    for (int t = 0; t < TT; t++)
        gemm_mma<256><<<dim3(gBlocks, 2), 256, GSMEM>>>(
            x_all + (size_t)t * NN * FIN, p_B1h, p_B1l, p_h[t], NN);
    convB_kernel<<<(128 * 64 + 255) / 256, 256>>>(W2, p_B2h, p_B2l, 128);
    for (int t = 0; t < TT; t++)
        dots_kernel<<<warpBlocks, 256>>>(p_h[t], att1, 2 * H1C, t);
    for (int t = 0; t < TT; t++)
        agg_kernel<H1C><<<warpBlocks, 256>>>(p_h[t], b1, p_mu1 + (size_t)t * NN * H1C, t);
    fuse_relu_kernel<<<(NN * H1C + 255) / 256, 256>>>(p_mu1);

    // layer 2
    for (int t = 0; t < TT; t++)
        gemm_mma<128><<<dim3(gBlocks, 1), 256, GSMEM>>>(
            p_mu1 + (size_t)t * NN * H1C, p_B2h, p_B2l, p_h[t], NN);
    for (int t = 0; t < TT; t++)
        dots_kernel<<<warpBlocks, 256>>>(p_h[t], att2, 2 * OUTC, t);
    for (int t = 0; t < TT; t++)
        agg_kernel<OUTC><<<warpBlocks, 256>>>(p_h[t], b2, p_mu2 + (size_t)t * NN * OUTC, t);

    final_kernel<<<(NN * OUTC + 255) / 256, 256>>>(p_mu2, out, out_size);
}